// round 6
// baseline (speedup 1.0000x reference)
#include <cuda_runtime.h>

#define YS 256
#define XS 16
#define TS 2048
#define TM1 2047

// Output packing (float32), reference return order:
// alpha (T*Y) | beta (T*Y) | p (1) | gamma (T*Y) | xi ((T-1)*Y*Y) | path (T)
#define OFF_ALPHA 0
#define OFF_BETA  (TS * YS)
#define OFF_P     (2 * TS * YS)
#define OFF_GAMMA (2 * TS * YS + 1)
#define OFF_XI    ((size_t)(3 * TS * YS + 1))
#define OFF_PATH  (OFF_XI + (size_t)TM1 * YS * YS)

// Scratch (static device memory — no allocations)
__device__ float g_bx[TS * YS];          // bx[t][j] = b[j, x[t]]
__device__ float g_At[YS * YS];          // A^T for the backward matvec
__device__ unsigned char g_bp[TM1 * YS]; // Viterbi backpointers (values 0..255)
__device__ float g_p;

// FTZ multiply: flushes denormal inputs and outputs (DAZ+FTZ), matching the
// XLA reference runtime's flush-to-zero elementwise f32 semantics. The Viterbi
// recursion decays through the denormal range; the underflow boundary state
// seeds the backtrack, so denormal handling must match the reference exactly.
__device__ __forceinline__ float fmul_ftz(float a, float b) {
    float r;
    asm("mul.rn.ftz.f32 %0, %1, %2;" : "=f"(r) : "f"(a), "f"(b));
    return r;
}

// ---------------------------------------------------------------- prep
__global__ void prep_bx_kernel(const int* __restrict__ x,
                               const float* __restrict__ b) {
    int t = blockIdx.x;
    int j = threadIdx.x;
    int xs = x[t];
    g_bx[t * YS + j] = b[j * XS + xs];
}

__global__ void transpose_kernel(const float* __restrict__ A) {
    int j = blockIdx.x;   // column of A = row of At
    int i = threadIdx.x;
    g_At[j * YS + i] = A[i * YS + j];
}

// ---------------------------------------------------------------- recurrences
// grid = 3 blocks x 256 threads. block 0: forward alpha (+p). block 1: backward
// beta. block 2: Viterbi (V recursion, backptrs, backtrack, path).
__global__ void recur_kernel(const float* __restrict__ A,
                             const float* __restrict__ pi,
                             float* __restrict__ out) {
    __shared__ __align__(16) float s_vec[YS];
    __shared__ __align__(16) float s_part[4][YS];
    __shared__ __align__(16) unsigned int s_partu[4][YS];
    __shared__ __align__(16) int   s_parti[4][YS];
    __shared__ float s_red[8];
    __shared__ unsigned int s_redu[8];
    __shared__ int   s_tz;
    __shared__ int   s_last;

    const int tid = threadIdx.x;          // 0..255
    const int pr  = tid >> 6;             // part 0..3 (i-range)
    const int jq  = tid & 63;
    const int j0  = jq * 4;               // 4 consecutive output columns

    if (blockIdx.x == 0) {
        // ---------------- forward: alpha[t] = (alpha[t-1] @ A) * bx[t]
        float a0 = g_bx[tid] * pi[tid];
        s_vec[tid] = a0;
        out[OFF_ALPHA + tid] = a0;
        __syncthreads();

        for (int t = 1; t < TS; ++t) {
            const float* Ab = A + (pr * 64) * YS + j0;
            float4 acc = make_float4(0.f, 0.f, 0.f, 0.f);
#pragma unroll 8
            for (int ii = 0; ii < 64; ++ii) {
                float av = s_vec[pr * 64 + ii];
                float4 a4 = __ldg((const float4*)(Ab + (size_t)ii * YS));
                acc.x = fmaf(av, a4.x, acc.x);
                acc.y = fmaf(av, a4.y, acc.y);
                acc.z = fmaf(av, a4.z, acc.z);
                acc.w = fmaf(av, a4.w, acc.w);
            }
            *(float4*)&s_part[pr][j0] = acc;
            __syncthreads();
            float s = s_part[0][tid] + s_part[1][tid] + s_part[2][tid] + s_part[3][tid];
            float an = s * g_bx[t * YS + tid];
            s_vec[tid] = an;
            out[OFF_ALPHA + t * YS + tid] = an;
            __syncthreads();
        }
        // p = sum(alpha[T-1])
        float v = s_vec[tid];
#pragma unroll
        for (int o = 16; o > 0; o >>= 1) v += __shfl_xor_sync(0xffffffffu, v, o);
        if ((tid & 31) == 0) s_red[tid >> 5] = v;
        __syncthreads();
        if (tid == 0) {
            float p = 0.f;
            for (int w = 0; w < 8; ++w) p += s_red[w];
            out[OFF_P] = p;
            g_p = p;
        }
    } else if (blockIdx.x == 1) {
        // ---------------- backward: beta[t] = A @ (bx[t+1] * beta[t+1])
        s_vec[tid] = 1.0f;
        out[OFF_BETA + (TS - 1) * YS + tid] = 1.0f;
        __syncthreads();

        for (int t = TS - 2; t >= 0; --t) {
            // w[j] = bx[t+1][j] * beta[t+1][j]  (in place, elementwise)
            s_vec[tid] = g_bx[(t + 1) * YS + tid] * s_vec[tid];
            __syncthreads();
            // beta_i = sum_j At[j][i] * w[j]   (output index = i, sum over j)
            const float* Ab = g_At + (pr * 64) * YS + j0;
            float4 acc = make_float4(0.f, 0.f, 0.f, 0.f);
#pragma unroll 8
            for (int jj = 0; jj < 64; ++jj) {
                float wv = s_vec[pr * 64 + jj];
                float4 a4 = __ldg((const float4*)(Ab + (size_t)jj * YS));
                acc.x = fmaf(wv, a4.x, acc.x);
                acc.y = fmaf(wv, a4.y, acc.y);
                acc.z = fmaf(wv, a4.z, acc.z);
                acc.w = fmaf(wv, a4.w, acc.w);
            }
            *(float4*)&s_part[pr][j0] = acc;
            __syncthreads();
            float bcur = s_part[0][tid] + s_part[1][tid] + s_part[2][tid] + s_part[3][tid];
            s_vec[tid] = bcur;
            out[OFF_BETA + t * YS + tid] = bcur;
            __syncthreads();
        }
    } else {
        // ---------------- Viterbi (FTZ fp32, uint-bitpattern first-max argmax)
        if (tid == 0) s_tz = -1;
        s_vec[tid] = g_bx[tid] * pi[tid];
        __syncthreads();

        int tzv = -1;
        for (int t = 1; t < TS; ++t) {
            const float* Ab = A + (pr * 64) * YS + j0;
            // running max as uint bit patterns (all values >= +0)
            unsigned int bmx = 0u, bmy = 0u, bmz = 0u, bmw = 0u;
            int bix = pr * 64, biy = pr * 64, biz = pr * 64, biw = pr * 64;
            for (int ii = 0; ii < 64; ++ii) {
                int i = pr * 64 + ii;
                float vv = s_vec[i];
                float4 a4 = __ldg((const float4*)(Ab + (size_t)ii * YS));
                unsigned int sx = __float_as_uint(fmul_ftz(vv, a4.x));
                unsigned int sy = __float_as_uint(fmul_ftz(vv, a4.y));
                unsigned int sz = __float_as_uint(fmul_ftz(vv, a4.z));
                unsigned int sw = __float_as_uint(fmul_ftz(vv, a4.w));
                if (sx > bmx) { bmx = sx; bix = i; }
                if (sy > bmy) { bmy = sy; biy = i; }
                if (sz > bmz) { bmz = sz; biz = i; }
                if (sw > bmw) { bmw = sw; biw = i; }
            }
            s_partu[pr][j0 + 0] = bmx;
            s_partu[pr][j0 + 1] = bmy;
            s_partu[pr][j0 + 2] = bmz;
            s_partu[pr][j0 + 3] = bmw;
            s_parti[pr][j0 + 0] = bix;
            s_parti[pr][j0 + 1] = biy;
            s_parti[pr][j0 + 2] = biz;
            s_parti[pr][j0 + 3] = biw;
            __syncthreads();
            // combine parts in ascending order (strict >) -> first-max index
            unsigned int m = s_partu[0][tid];
            int idx = s_parti[0][tid];
#pragma unroll
            for (int p = 1; p < 4; ++p) {
                unsigned int mp = s_partu[p][tid];
                if (mp > m) { m = mp; idx = s_parti[p][tid]; }
            }
            float vn = fmul_ftz(g_bx[t * YS + tid], __uint_as_float(m));
            g_bp[(t - 1) * YS + tid] = (unsigned char)idx;
            // all-zero detection via OR of bit patterns (values are +0 or >0)
            unsigned int ob = __reduce_or_sync(0xffffffffu, __float_as_uint(vn));
            if ((tid & 31) == 0) s_redu[tid >> 5] = ob;
            s_vec[tid] = vn;
            __syncthreads();
            if (tid == 0) {
                unsigned int oo = 0u;
                for (int w = 0; w < 8; ++w) oo |= s_redu[w];
                if (oo == 0u) s_tz = t;
            }
            __syncthreads();
            if (s_tz >= 0) { tzv = s_tz; break; }
        }

        // fill remaining backptr rows with 0 (V is all-zero from tzv onward,
        // so argmax of all-zero scores = 0 for every column)
        if (tzv >= 0 && tzv <= TS - 2) {
            unsigned int* bp32 = (unsigned int*)(g_bp + tzv * YS);
            int n32 = (TM1 - tzv) * YS / 4;
            for (int k = tid; k < n32; k += YS) bp32[k] = 0u;
        }
        __syncthreads();

        // last = argmax(V_last), first-max (uint compare)
        if (tid == 0) {
            if (tzv >= 0) {
                s_last = 0;
            } else {
                unsigned int m = __float_as_uint(s_vec[0]);
                int idx = 0;
                for (int i = 1; i < YS; ++i) {
                    unsigned int vi = __float_as_uint(s_vec[i]);
                    if (vi > m) { m = vi; idx = i; }
                }
                s_last = idx;
            }
        }
        __syncthreads();
        int last = s_last;

        // path zeros for [tzv, T-1) when underflowed (backtrack through
        // all-zero bp rows stays at state 0)
        if (tzv >= 0) {
            for (int k = tzv + tid; k < TS - 1; k += YS)
                out[OFF_PATH + k] = 0.0f;
        }
        if (tid == 0) {
            out[OFF_PATH + TS - 1] = (float)last;
            int s = last;
            int tstart = (tzv >= 0) ? (tzv - 1) : (TS - 2);
            for (int t = tstart; t >= 0; --t) {
                s = (int)g_bp[t * YS + s];
                out[OFF_PATH + t] = (float)s;
            }
        }
    }
}

// ---------------------------------------------------------------- gamma
__global__ void gamma_kernel(float* __restrict__ out) {
    int idx = blockIdx.x * YS + threadIdx.x;
    float p = g_p;
    out[OFF_GAMMA + idx] = out[OFF_ALPHA + idx] * out[OFF_BETA + idx] / p;
}

// ---------------------------------------------------------------- xi
// block t in [0, T-2]; xi[t][i][j] = (alpha[t][i] * A[i][j]) * (bx[t+1][j]*beta[t+1][j])
// NOTE: OFF_XI is an odd float offset (the scalar p shifts it by 4 bytes), so
// the xi region is only 4-byte aligned -> scalar STG.32 only, fully coalesced.
__global__ void xi_kernel(const float* __restrict__ A, float* __restrict__ out) {
    __shared__ __align__(16) float s_a[YS];
    __shared__ __align__(16) float s_w[YS];
    int t = blockIdx.x;
    int tid = threadIdx.x;

    s_a[tid] = out[OFF_ALPHA + t * YS + tid];
    s_w[tid] = g_bx[(t + 1) * YS + tid] * out[OFF_BETA + (t + 1) * YS + tid];
    __syncthreads();

    float wj = s_w[tid];
    float* ob = out + OFF_XI + (size_t)t * YS * YS + tid;
    const float* Ac = A + tid;
#pragma unroll 8
    for (int i = 0; i < YS; ++i) {
        float ai = s_a[i];
        float av = __ldg(Ac + (size_t)i * YS);
        ob[(size_t)i * YS] = (ai * av) * wj;
    }
}

// ---------------------------------------------------------------- launch
extern "C" void kernel_launch(void* const* d_in, const int* in_sizes, int n_in,
                              void* d_out, int out_size) {
    const int*   x  = (const int*)d_in[0];
    const float* A  = (const float*)d_in[1];
    const float* b  = (const float*)d_in[2];
    const float* pi = (const float*)d_in[3];
    float* out = (float*)d_out;

    prep_bx_kernel<<<TS, YS>>>(x, b);
    transpose_kernel<<<YS, YS>>>(A);
    recur_kernel<<<3, YS>>>(A, pi, out);
    gamma_kernel<<<TS, YS>>>(out);
    xi_kernel<<<TM1, YS>>>(A, out);
}

// round 7
// speedup vs baseline: 5.9424x; 5.9424x over previous
#include <cuda_runtime.h>

#define YS 256
#define XS 16
#define TS 2048
#define TM1 2047

// Output packing (float32), reference return order:
// alpha (T*Y) | beta (T*Y) | p (1) | gamma (T*Y) | xi ((T-1)*Y*Y) | path (T)
#define OFF_ALPHA 0
#define OFF_BETA  (TS * YS)
#define OFF_P     (2 * TS * YS)
#define OFF_GAMMA (2 * TS * YS + 1)
#define OFF_XI    ((size_t)(3 * TS * YS + 1))
#define OFF_PATH  (OFF_XI + (size_t)TM1 * YS * YS)

#define MSTRIDE 36   // padded row stride (floats) for bank-conflict-free LDS.128

// Scratch (static device memory — no allocations)
__device__ float g_bx[TS * YS];          // bx[t][j] = b[j, x[t]]
__device__ unsigned char g_bp[TM1 * YS]; // Viterbi backpointers (values 0..255)
__device__ float g_p;

// FTZ multiply (flush denormals) — matches the reference runtime's f32 flush
// semantics in the Viterbi decay-to-zero zone. Verified bit-exact in R6.
__device__ __forceinline__ float fmul_ftz(float a, float b) {
    float r;
    asm("mul.rn.ftz.f32 %0, %1, %2;" : "=f"(r) : "f"(a), "f"(b));
    return r;
}

__device__ __forceinline__ unsigned int smem_u32(const void* p) {
    unsigned int a;
    asm("{ .reg .u64 t; cvta.to.shared.u64 t, %1; cvt.u32.u64 %0, t; }"
        : "=r"(a) : "l"(p));
    return a;
}

__device__ __forceinline__ unsigned int ctarank() {
    unsigned int r;
    asm("mov.u32 %0, %%cluster_ctarank;" : "=r"(r));
    return r;
}

// Remote (DSMEM) float4 store to the same smem offset in cluster CTA `rank`.
__device__ __forceinline__ void sts_cluster_f4(unsigned int saddr, unsigned int rank,
                                               float x, float y, float z, float w) {
    asm volatile(
        "{ .reg .b32 r; mapa.shared::cluster.u32 r, %0, %1;\n\t"
        "st.shared::cluster.v4.f32 [r], {%2,%3,%4,%5}; }"
        :: "r"(saddr), "r"(rank), "f"(x), "f"(y), "f"(z), "f"(w) : "memory");
}

#define CLUSTER_ARRIVE() asm volatile("barrier.cluster.arrive.aligned;" ::: "memory")
#define CLUSTER_WAIT()   asm volatile("barrier.cluster.wait.aligned;" ::: "memory")

// ---------------------------------------------------------------- prep
__global__ void prep_bx_kernel(const int* __restrict__ x,
                               const float* __restrict__ b) {
    int t = blockIdx.x;
    int j = threadIdx.x;
    g_bx[t * YS + j] = b[j * XS + x[t]];
}

// ---------------------------------------------------------------- recurrences
// grid = 24 CTAs = 3 clusters of 8. Cluster r: 0=alpha, 1=beta, 2=Viterbi.
// CTA g of a cluster owns output columns [g*32, g*32+32) with its matrix slice
// resident in SMEM. Per step: compute 32 outputs from the full 256-vector in
// local SMEM, push them to every cluster CTA's ping-pong next-buffer via
// DSMEM, one cluster barrier per step.
__global__ void __cluster_dims__(8, 1, 1)
recur_cluster_kernel(const float* __restrict__ A,
                     const float* __restrict__ pi,
                     float* __restrict__ out) {
    __shared__ __align__(16) float Ms[YS * MSTRIDE];  // 36 KB slice
    __shared__ __align__(16) float s_buf[2][YS];      // ping-pong full vector
    __shared__ unsigned int s_redu[8];
    __shared__ float s_redf[8];
    __shared__ int s_dead;
    __shared__ int s_last;

    const int tid  = threadIdx.x;
    const int w    = tid >> 5;
    const int lane = tid & 31;
    const int c0   = w * 4;                 // local column quad
    const unsigned int g = ctarank();
    const int r    = blockIdx.x >> 3;       // recursion id
    const int colg = (int)g * 32 + c0;      // global column base of this warp

    const unsigned int bufu0 = smem_u32(&s_buf[0][0]);
    const unsigned int bufu1 = smem_u32(&s_buf[1][0]);

    // ---- load matrix slice into SMEM ----
    if (r != 1) {
        // alpha/viterbi: Ms[k][c] = A[k][g*32+c]   (out_c = sum_k v[k]*A[k][c])
        for (int idx = tid; idx < YS * 32; idx += YS) {
            int k = idx >> 5, c = idx & 31;
            Ms[k * MSTRIDE + c] = A[k * YS + (int)g * 32 + c];
        }
    } else {
        // beta: Ms[k][c] = A[g*32+c][k]            (out_c = sum_k w[k]*A[c][k])
        for (int cc = 0; cc < 32; ++cc)
            Ms[tid * MSTRIDE + cc] = A[((int)g * 32 + cc) * YS + tid];
    }

    // ---- init v0 and boundary rows ----
    if (r == 0) {
        float a0 = g_bx[tid] * pi[tid];
        s_buf[0][tid] = a0;
        if (g == 0) out[OFF_ALPHA + tid] = a0;
    } else if (r == 1) {
        s_buf[0][tid] = g_bx[(TS - 1) * YS + tid];   // w[T-1] = bx[T-1] * 1
        if (g == 0) out[OFF_BETA + (TS - 1) * YS + tid] = 1.0f;
    } else {
        s_buf[0][tid] = g_bx[tid] * pi[tid];
    }
    if (tid == 0) { s_dead = 0; s_last = 0; }
    __syncthreads();
    CLUSTER_ARRIVE();
    CLUSTER_WAIT();

    const int S = TS - 1;  // 2047 steps
    int tz = -1;

    // bx prefetch for step 0
    int t0 = (r == 1) ? (TS - 2) : 1;
    float4 bxv = __ldg((const float4*)&g_bx[t0 * YS + colg]);

    for (int s = 0; s < S; ++s) {
        const int cur = s & 1;
        const unsigned int nxtu = (cur ? bufu0 : bufu1);
        const int t = (r == 1) ? (TS - 2 - s) : (s + 1);

        // gather v into registers (k = kk*32 + lane)
        float vreg[8];
        unsigned int orv = 0u;
#pragma unroll
        for (int kk = 0; kk < 8; ++kk) {
            vreg[kk] = s_buf[cur][kk * 32 + lane];
            orv |= __float_as_uint(vreg[kk]);
        }

        if (r == 2) {
            // all-zero detection (identical buffers in every CTA -> uniform)
            unsigned int o = __reduce_or_sync(0xffffffffu, orv);
            if (lane == 0) s_redu[w] = o;
            __syncthreads();
            if (tid == 0) {
                unsigned int oo = 0u;
                for (int i = 0; i < 8; ++i) oo |= s_redu[i];
                if (oo == 0u) s_dead = 1;
            }
            __syncthreads();
            if (s_dead) { tz = s; break; }
        }

        if (r != 2) {
            float4 acc = make_float4(0.f, 0.f, 0.f, 0.f);
#pragma unroll
            for (int kk = 0; kk < 8; ++kk) {
                float vv = vreg[kk];
                float4 m = *(const float4*)&Ms[(kk * 32 + lane) * MSTRIDE + c0];
                acc.x = fmaf(vv, m.x, acc.x);
                acc.y = fmaf(vv, m.y, acc.y);
                acc.z = fmaf(vv, m.z, acc.z);
                acc.w = fmaf(vv, m.w, acc.w);
            }
#pragma unroll
            for (int off = 16; off > 0; off >>= 1) {
                acc.x += __shfl_xor_sync(0xffffffffu, acc.x, off);
                acc.y += __shfl_xor_sync(0xffffffffu, acc.y, off);
                acc.z += __shfl_xor_sync(0xffffffffu, acc.z, off);
                acc.w += __shfl_xor_sync(0xffffffffu, acc.w, off);
            }
            // pushed value always includes the bx factor for the NEXT step
            float4 push;
            push.x = acc.x * bxv.x;
            push.y = acc.y * bxv.y;
            push.z = acc.z * bxv.z;
            push.w = acc.w * bxv.w;
            if (lane == 0) {
                if (r == 0)
                    *(float4*)&out[OFF_ALPHA + t * YS + colg] = push;  // alpha = sum*bx
                else
                    *(float4*)&out[OFF_BETA + t * YS + colg] = acc;   // beta raw
            }
            if (lane < 8)
                sts_cluster_f4(nxtu + (unsigned int)colg * 4u, lane,
                               push.x, push.y, push.z, push.w);
        } else {
            // Viterbi: max/argmax over k, FTZ muls, first-max tie semantics
            unsigned int bu[4] = {0u, 0u, 0u, 0u};
            int bi[4] = {lane, lane, lane, lane};
#pragma unroll
            for (int kk = 0; kk < 8; ++kk) {
                int k = kk * 32 + lane;
                float vv = vreg[kk];
                float4 m = *(const float4*)&Ms[k * MSTRIDE + c0];
                unsigned int s0 = __float_as_uint(fmul_ftz(vv, m.x));
                unsigned int s1 = __float_as_uint(fmul_ftz(vv, m.y));
                unsigned int s2 = __float_as_uint(fmul_ftz(vv, m.z));
                unsigned int s3 = __float_as_uint(fmul_ftz(vv, m.w));
                if (s0 > bu[0]) { bu[0] = s0; bi[0] = k; }
                if (s1 > bu[1]) { bu[1] = s1; bi[1] = k; }
                if (s2 > bu[2]) { bu[2] = s2; bi[2] = k; }
                if (s3 > bu[3]) { bu[3] = s3; bi[3] = k; }
            }
#pragma unroll
            for (int off = 16; off > 0; off >>= 1) {
#pragma unroll
                for (int j = 0; j < 4; ++j) {
                    unsigned int ou = __shfl_xor_sync(0xffffffffu, bu[j], off);
                    int oi = __shfl_xor_sync(0xffffffffu, bi[j], off);
                    if (ou > bu[j] || (ou == bu[j] && oi < bi[j])) {
                        bu[j] = ou; bi[j] = oi;
                    }
                }
            }
            float4 push;
            push.x = fmul_ftz(bxv.x, __uint_as_float(bu[0]));
            push.y = fmul_ftz(bxv.y, __uint_as_float(bu[1]));
            push.z = fmul_ftz(bxv.z, __uint_as_float(bu[2]));
            push.w = fmul_ftz(bxv.w, __uint_as_float(bu[3]));
            if (lane < 8)
                sts_cluster_f4(nxtu + (unsigned int)colg * 4u, lane,
                               push.x, push.y, push.z, push.w);
            if (lane == 8) {
                unsigned int pack = (unsigned int)bi[0] | ((unsigned int)bi[1] << 8)
                                  | ((unsigned int)bi[2] << 16) | ((unsigned int)bi[3] << 24);
                *(unsigned int*)(g_bp + (size_t)(t - 1) * YS + colg) = pack;
            }
        }

        CLUSTER_ARRIVE();
        if (s + 1 < S) {
            int tn = (r == 1) ? (TS - 2 - (s + 1)) : (s + 2);
            bxv = __ldg((const float4*)&g_bx[tn * YS + colg]);
        }
        CLUSTER_WAIT();
    }

    // ---- epilogues ----
    if (r == 0) {
        // p = sum(alpha[T-1]); final pushed buffer parity = S&1 = 1
        if (g == 0) {
            float v = s_buf[1][tid];
#pragma unroll
            for (int off = 16; off > 0; off >>= 1)
                v += __shfl_xor_sync(0xffffffffu, v, off);
            if (lane == 0) s_redf[w] = v;
            __syncthreads();
            if (tid == 0) {
                float p = 0.f;
                for (int i = 0; i < 8; ++i) p += s_redf[i];
                out[OFF_P] = p;
                g_p = p;
            }
        }
    } else if (r == 2) {
        // zero-fill bp rows [tz, TM1) across the cluster (V dead from tz on)
        if (tz >= 0) {
            unsigned int* bp32 = (unsigned int*)(g_bp + (size_t)tz * YS);
            int n32 = (TM1 - tz) * (YS / 4);
            for (int i = (int)g * YS + tid; i < n32; i += 8 * YS) bp32[i] = 0u;
        }
        CLUSTER_ARRIVE();
        CLUSTER_WAIT();
        if (g == 0) {
            if (tz >= 0) {
                for (int k = tz + tid; k < TS - 1; k += YS)
                    out[OFF_PATH + k] = 0.0f;
                // s_last already 0
            } else if (tid == 0) {
                unsigned int m = __float_as_uint(s_buf[1][0]);
                int idx = 0;
                for (int i = 1; i < YS; ++i) {
                    unsigned int vi = __float_as_uint(s_buf[1][i]);
                    if (vi > m) { m = vi; idx = i; }
                }
                s_last = idx;
            }
            __syncthreads();
            if (tid == 0) {
                int last = s_last;
                out[OFF_PATH + TS - 1] = (float)last;
                int st = last;
                int tstart = (tz >= 0) ? (tz - 1) : (TS - 2);
                for (int t = tstart; t >= 0; --t) {
                    st = (int)g_bp[(size_t)t * YS + st];
                    out[OFF_PATH + t] = (float)st;
                }
            }
        }
    }
}

// ---------------------------------------------------------------- gamma
__global__ void gamma_kernel(float* __restrict__ out) {
    int idx = blockIdx.x * YS + threadIdx.x;
    float p = g_p;
    out[OFF_GAMMA + idx] = out[OFF_ALPHA + idx] * out[OFF_BETA + idx] / p;
}

// ---------------------------------------------------------------- xi
// block t in [0, T-2]; xi[t][i][j] = (alpha[t][i] * A[i][j]) * (bx[t+1][j]*beta[t+1][j])
// OFF_XI is an odd float offset -> 4-byte aligned region -> scalar STG.32 only.
__global__ void xi_kernel(const float* __restrict__ A, float* __restrict__ out) {
    __shared__ __align__(16) float s_a[YS];
    __shared__ __align__(16) float s_w[YS];
    int t = blockIdx.x;
    int tid = threadIdx.x;

    s_a[tid] = out[OFF_ALPHA + t * YS + tid];
    s_w[tid] = g_bx[(t + 1) * YS + tid] * out[OFF_BETA + (t + 1) * YS + tid];
    __syncthreads();

    float wj = s_w[tid];
    float* ob = out + OFF_XI + (size_t)t * YS * YS + tid;
    const float* Ac = A + tid;
#pragma unroll 8
    for (int i = 0; i < YS; ++i) {
        float ai = s_a[i];
        float av = __ldg(Ac + (size_t)i * YS);
        ob[(size_t)i * YS] = (ai * av) * wj;
    }
}

// ---------------------------------------------------------------- launch
extern "C" void kernel_launch(void* const* d_in, const int* in_sizes, int n_in,
                              void* d_out, int out_size) {
    const int*   x  = (const int*)d_in[0];
    const float* A  = (const float*)d_in[1];
    const float* b  = (const float*)d_in[2];
    const float* pi = (const float*)d_in[3];
    float* out = (float*)d_out;

    prep_bx_kernel<<<TS, YS>>>(x, b);
    recur_cluster_kernel<<<24, YS>>>(A, pi, out);
    gamma_kernel<<<TS, YS>>>(out);
    xi_kernel<<<TM1, YS>>>(A, out);
}